// round 11
// baseline (speedup 1.0000x reference)
#include <cuda_runtime.h>
#include <cuda_fp16.h>
#include <cstdint>

// ---------------- problem constants ----------------
#define IN_CH   256
#define BATCH   8
#define KF      2304            // 9*256
#define NOUT    512
#define L2D     1024
#define MROWS   (BATCH * L2D)   // 8192
#define NCHK    (KF / 64)       // 36 k-chunks of 64 (64 fp16 = 128B row)

// GEMM tiling: CTA 128(M) x 256(N), 8 warps (2m x 4n) of 64x64
#define NS   4                  // pipeline stages
#define TSZA (128 * 128)        // 16KB: 128 rows x 128B
#define TSZB (256 * 128)        // 32KB: 256 rows x 128B
#define STAGE (TSZA + TSZB)     // 48KB
#define SMEM_TOTAL (NS * STAGE) // 192KB

// scratch (__device__ globals: allocation-free rule)
__device__ __align__(16) __half g_B16[(size_t)NOUT * KF];   // B^T chunked fp16

// ---------------- helpers ----------------
__device__ __forceinline__ uint32_t h2u(__half2 h) {
    uint32_t u;
    __builtin_memcpy(&u, &h, 4);
    return u;
}
__device__ __forceinline__ void cpa16(uint32_t dst, const void* src) {
    asm volatile("cp.async.cg.shared.global [%0], [%1], 16;" :: "r"(dst), "l"(src));
}
#define CP_COMMIT() asm volatile("cp.async.commit_group;" ::: "memory")
#define CP_WAITN()  asm volatile("cp.async.wait_group %0;" :: "n"(NS - 2) : "memory")

// swizzled smem row of 128B; w = 4-byte word index 0..31
__device__ __forceinline__ uint32_t lds32(const char* base, int row, int w) {
    return *(const uint32_t*)(base + row * 128 + (((w >> 2) ^ (row & 7)) << 4) + ((w & 3) << 2));
}
__device__ __forceinline__ void mma16f(float* c, const uint32_t* a, const uint32_t* b) {
    asm volatile(
        "mma.sync.aligned.m16n8k16.row.col.f32.f16.f16.f32 "
        "{%0,%1,%2,%3}, {%4,%5,%6,%7}, {%8,%9}, {%0,%1,%2,%3};"
        : "+f"(c[0]), "+f"(c[1]), "+f"(c[2]), "+f"(c[3])
        : "r"(a[0]), "r"(a[1]), "r"(a[2]), "r"(a[3]), "r"(b[0]), "r"(b[1]));
}

// ---------------------------------------------------------------------------
// Kernel 1: B^T expansion -> chunked fp16. BT[co][k] = w[p][q][(j-m)&63]
// ---------------------------------------------------------------------------
__global__ void beffT_kernel(const float* __restrict__ wgt) {
    const int co = blockIdx.y;
    const int k = blockIdx.x * 256 + threadIdx.x;
    const int q = k >> 6, m = k & 63;
    const int p = co >> 6, j = co & 63;
    float v = wgt[((p * 36 + q) << 6) + ((j - m) & 63)];
    g_B16[(((size_t)co * NCHK + (k >> 6)) << 6) + (k & 63)] = __float2half(v);
}

// ---------------------------------------------------------------------------
// Kernel 2: fused im2col + fp16 mma.sync GEMM + transpose store.
// A chunk (row r, k in [c*64,(c+1)*64)) == one (b, f, l0..l0+63) span of the
// virtual im2col buffer == two 32-pixel x-rows with uniform (oy, ox) shift.
// Thread (m = tid>>1, half = tid&1) gathers one 32-pixel row per chunk.
// ---------------------------------------------------------------------------
__global__ void __launch_bounds__(256, 1) gemm_kernel(const float* __restrict__ x,
                                                      float* __restrict__ out) {
    extern __shared__ char sm[];
    const int tid = threadIdx.x;
    const int lane = tid & 31;
    const int wid = tid >> 5;
    const int g = lane >> 2, t = lane & 3;
    const int wm = wid >> 2, wn = wid & 3;       // 2m x 4n
    const int bm = blockIdx.y * 128;
    const int bn = blockIdx.x * 256;

    const int am = tid >> 1, ahalf = tid & 1;    // A-gather row / half assignment

    float acc[4][8][4];
    #pragma unroll
    for (int i = 0; i < 4; i++)
        #pragma unroll
        for (int j = 0; j < 8; j++)
            #pragma unroll
            for (int q = 0; q < 4; q++) acc[i][j][q] = 0.0f;

    // held A-gather state (one chunk in flight)
    float4 v4[8];
    int aox = 0;

    // ---- A gather: issue LDGs for chunk cc into v4 (held across compute) ----
    auto lda = [&](int cc) {
        const uint32_t ib = (uint32_t)(bm + am) * KF + (uint32_t)cc * 64;
        const uint32_t bf = ib >> 10;
        const uint32_t b_ = bf / KF;
        const uint32_t f  = bf - b_ * KF;
        const uint32_t ci = f / 9;
        const uint32_t dd = f - ci * 9;
        const int oy = (int)(dd / 3) - 1;
        aox = (int)(dd % 3) - 1;
        const int h = (int)((ib & 1023) >> 5) + ahalf;
        const int y = h + oy;
        const bool yok = (unsigned)y < 32u;
        const float4* src = (const float4*)(x + ((b_ * IN_CH + ci) << 10) + (y << 5));
        #pragma unroll
        for (int i = 0; i < 8; i++)
            v4[i] = yok ? src[i] : make_float4(0.f, 0.f, 0.f, 0.f);
    };

    // ---- A store: shift by aox, cvt fp16, swizzled STS.128 x4 into stage ss ----
    auto sta = [&](int ss) {
        char* As = sm + ss * STAGE;
        const float* vf = (const float*)v4;
        float s[32];
        if (aox == 0) {
            #pragma unroll
            for (int e = 0; e < 32; e++) s[e] = vf[e];
        } else if (aox < 0) {
            s[0] = 0.f;
            #pragma unroll
            for (int e = 1; e < 32; e++) s[e] = vf[e - 1];
        } else {
            #pragma unroll
            for (int e = 0; e < 31; e++) s[e] = vf[e + 1];
            s[31] = 0.f;
        }
        #pragma unroll
        for (int q = 0; q < 4; q++) {
            uint4 pk;
            pk.x = h2u(__floats2half2_rn(s[q * 8 + 0], s[q * 8 + 1]));
            pk.y = h2u(__floats2half2_rn(s[q * 8 + 2], s[q * 8 + 3]));
            pk.z = h2u(__floats2half2_rn(s[q * 8 + 4], s[q * 8 + 5]));
            pk.w = h2u(__floats2half2_rn(s[q * 8 + 6], s[q * 8 + 7]));
            const int cj = ahalf * 4 + q;
            *(uint4*)(As + am * 128 + ((cj ^ (am & 7)) << 4)) = pk;
        }
    };

    // ---- B load via cp.async (unchanged) ----
    auto ldb = [&](int c, int ss) {
        char* Bs = sm + ss * STAGE + TSZA;
        #pragma unroll
        for (int i = 0; i < 8; i++) {            // B: 256 rows x 8 x 16B
            int id = tid + i * 256;
            int row = id >> 3, cj = id & 7;
            uint32_t swo = (uint32_t)(row * 128 + ((cj ^ (row & 7)) << 4));
            cpa16((uint32_t)__cvta_generic_to_shared(Bs + swo),
                  &g_B16[(((size_t)(bn + row) * NCHK + c) << 6) + (cj << 3)]);
        }
    };

    auto compute = [&](int ss) {
        const char* As = sm + ss * STAGE;
        const char* Bs = As + TSZA;
        #pragma unroll
        for (int ka = 0; ka < 4; ka++) {         // 4 k16 atoms per 64-chunk
            const int kw = ka * 8;
            uint32_t a[4][4], bb[8][2];
            #pragma unroll
            for (int ma = 0; ma < 4; ma++) {
                int r0 = wm * 64 + ma * 16 + g;
                a[ma][0] = lds32(As, r0,     kw + t);
                a[ma][1] = lds32(As, r0 + 8, kw + t);
                a[ma][2] = lds32(As, r0,     kw + t + 4);
                a[ma][3] = lds32(As, r0 + 8, kw + t + 4);
            }
            #pragma unroll
            for (int na = 0; na < 8; na++) {
                int n0 = wn * 64 + na * 8 + g;
                bb[na][0] = lds32(Bs, n0, kw + t);
                bb[na][1] = lds32(Bs, n0, kw + t + 4);
            }
            #pragma unroll
            for (int ma = 0; ma < 4; ma++)
                #pragma unroll
                for (int na = 0; na < 8; na++)
                    mma16f(acc[ma][na], a[ma], bb[na]);
        }
    };

    // prologue: fill first NS-1 stages (A gathered+stored, B committed)
    #pragma unroll
    for (int s = 0; s < NS - 1; s++) {
        lda(s); sta(s);
        ldb(s, s); CP_COMMIT();
    }
    lda(NS - 1);                                 // A of stage NS-1 held in regs
    __syncthreads();                             // A stages 0..NS-2 visible

    for (int c = 0; c < NCHK; c++) {
        CP_WAITN();
        __syncthreads();
        const int cs = c + NS - 1;
        if (cs < NCHK) sta(cs & 3);              // STS held A into freed stage
        if (c + NS < NCHK) lda(c + NS);          // issue next A gather (held)
        if (cs < NCHK) { ldb(cs, cs & 3); CP_COMMIT(); }
        compute(c & 3);
    }

    // epilogue: C[r][co] -> out[b][co][l2], r = b*1024 + l2
    #pragma unroll
    for (int ma = 0; ma < 4; ma++) {
        #pragma unroll
        for (int half = 0; half < 2; half++) {
            const int r = bm + wm * 64 + ma * 16 + g + half * 8;
            const int b = r >> 10;
            const int l2 = r & (L2D - 1);
            float* op = out + (((size_t)b * NOUT) << 10) + l2;
            #pragma unroll
            for (int na = 0; na < 8; na++) {
                const int co = bn + wn * 64 + na * 8 + t * 2;
                op[(size_t)co << 10]       = acc[ma][na][half * 2 + 0];
                op[(size_t)(co + 1) << 10] = acc[ma][na][half * 2 + 1];
            }
        }
    }
}

// ---------------------------------------------------------------------------
extern "C" void kernel_launch(void* const* d_in, const int* in_sizes, int n_in,
                              void* d_out, int out_size) {
    const float* x = (const float*)d_in[0];
    const float* w = (const float*)d_in[1];
    if (n_in >= 2 && in_sizes[0] == 8 * 36 * 64) {   // defensive swap by size
        const float* tp = x; x = w; w = tp;
    }
    float* out = (float*)d_out;

    cudaFuncSetAttribute(gemm_kernel, cudaFuncAttributeMaxDynamicSharedMemorySize, SMEM_TOTAL);

    beffT_kernel<<<dim3(KF / 256, NOUT), 256>>>(w);
    gemm_kernel<<<dim3(NOUT / 256, MROWS / 128), 256, SMEM_TOTAL>>>(x, out);
    (void)out_size;
}

// round 12
// speedup vs baseline: 1.4033x; 1.4033x over previous
#include <cuda_runtime.h>
#include <cuda_fp16.h>
#include <cstdint>

// ---------------- problem constants ----------------
#define IN_CH   256
#define BATCH   8
#define KF      2304            // 9*256
#define NOUT    512
#define L2D     1024
#define MROWS   (BATCH * L2D)   // 8192
#define NCHK    (KF / 64)       // 36 k-chunks of 64 (64 fp16 = 128B row)

// GEMM tiling: CTA 128(M) x 256(N), 8 warps (2m x 4n) of 64x64
#define NS   4                  // cp.async pipeline stages
#define TSZA (128 * 128)        // 16KB: 128 rows x 128B
#define TSZB (256 * 128)        // 32KB: 256 rows x 128B
#define STAGE (TSZA + TSZB)     // 48KB
#define SMEM_TOTAL (NS * STAGE) // 192KB

// scratch (__device__ globals: allocation-free rule)
__device__ __align__(16) __half g_A16[(size_t)MROWS * KF];
__device__ __align__(16) __half g_B16[(size_t)NOUT * KF];

// ---------------- helpers ----------------
__device__ __forceinline__ uint32_t h2u(__half2 h) {
    uint32_t u;
    __builtin_memcpy(&u, &h, 4);
    return u;
}
__device__ __forceinline__ void cpa16(uint32_t dst, const void* src) {
    asm volatile("cp.async.cg.shared.global [%0], [%1], 16;" :: "r"(dst), "l"(src));
}
#define CP_COMMIT() asm volatile("cp.async.commit_group;" ::: "memory")
#define CP_WAITN()  asm volatile("cp.async.wait_group %0;" :: "n"(NS - 2) : "memory")

__device__ __forceinline__ void ldm4(uint32_t* r, uint32_t addr) {
    asm volatile("ldmatrix.sync.aligned.m8n8.x4.shared.b16 {%0,%1,%2,%3}, [%4];"
                 : "=r"(r[0]), "=r"(r[1]), "=r"(r[2]), "=r"(r[3]) : "r"(addr));
}
__device__ __forceinline__ void mma16f(float* c, const uint32_t* a, const uint32_t* b) {
    asm volatile(
        "mma.sync.aligned.m16n8k16.row.col.f32.f16.f16.f32 "
        "{%0,%1,%2,%3}, {%4,%5,%6,%7}, {%8,%9}, {%0,%1,%2,%3};"
        : "+f"(c[0]), "+f"(c[1]), "+f"(c[2]), "+f"(c[3])
        : "r"(a[0]), "r"(a[1]), "r"(a[2]), "r"(a[3]), "r"(b[0]), "r"(b[1]));
}

// ---------------------------------------------------------------------------
// Kernel 1: im2col -> chunked fp16, 4 elems/thread, one 8B store.
// ---------------------------------------------------------------------------
__global__ void im2col_kernel(const float* __restrict__ x) {
    const int dd = blockIdx.x, ci = blockIdx.y, b = blockIdx.z;
    const int oy = dd / 3 - 1, ox = dd % 3 - 1;          // uniform per block
    const float* xp = x + (((size_t)(b * IN_CH + ci)) << 10);
    const uint32_t ibase = ((uint32_t)(b * KF + ci * 9 + dd)) << 10;
    const uint32_t r0 = ibase / KF, k0 = ibase % KF;     // uniform per block

    const int l = threadIdx.x << 2;                      // 0,4,...,1020
    const int h = l >> 5, w = l & 31;                    // w multiple of 4
    const int y = h + oy;
    const bool yok = (unsigned)y < 32u;
    const float* rowp = xp + (y << 5) + (w + ox);
    float v[4];
    #pragma unroll
    for (int e = 0; e < 4; e++) {
        int xw = w + ox + e;
        v[e] = (yok && (unsigned)xw < 32u) ? rowp[e] : 0.0f;
    }
    uint32_t k = k0 + (uint32_t)l, r = r0;
    if (k >= KF) { k -= KF; r++; }
    uint2 pk;
    pk.x = h2u(__floats2half2_rn(v[0], v[1]));
    pk.y = h2u(__floats2half2_rn(v[2], v[3]));
    *(uint2*)&g_A16[(((size_t)r * NCHK + (k >> 6)) << 6) + (k & 63)] = pk;
}

// ---------------------------------------------------------------------------
// Kernel 2: B^T expansion -> chunked fp16. BT[co][k] = w[p][q][(j-m)&63]
// ---------------------------------------------------------------------------
__global__ void beffT_kernel(const float* __restrict__ wgt) {
    const int co = blockIdx.y;
    const int k = blockIdx.x * 256 + threadIdx.x;
    const int q = k >> 6, m = k & 63;
    const int p = co >> 6, j = co & 63;
    float v = wgt[((p * 36 + q) << 6) + ((j - m) & 63)];
    g_B16[(((size_t)co * NCHK + (k >> 6)) << 6) + (k & 63)] = __float2half(v);
}

// ---------------------------------------------------------------------------
// Kernel 3: fp16 mma.sync GEMM with ldmatrix fragment loads.
// CTA 128x256, 8 warps (2m x 4n) of 64x64, 4-stage cp.async.
// Per-lane ldmatrix base addresses precomputed; per-ka addr = base ^ (ka<<5).
// ---------------------------------------------------------------------------
__global__ void __launch_bounds__(256, 1) gemm_kernel(float* __restrict__ out) {
    extern __shared__ char sm[];
    const uint32_t sbase = (uint32_t)__cvta_generic_to_shared(sm);
    const int tid = threadIdx.x;
    const int lane = tid & 31;
    const int wid = tid >> 5;
    const int g = lane >> 2, t = lane & 3;
    const int wm = wid >> 2, wn = wid & 3;       // 2m x 4n
    const int bm = blockIdx.y * 128;
    const int bn = blockIdx.x * 256;

    // ldmatrix per-lane base offsets (within a stage), ka=0
    // A tiles (per ma): matrices {m0-7 k0, m8-15 k0, m0-7 k8, m8-15 k8}
    uint32_t abase[4], bbase[4];
    {
        const int arow0 = wm * 64 + (lane & 7) + ((lane >> 3) & 1) * 8;
        const int ahi   = lane >> 4;
        #pragma unroll
        for (int ma = 0; ma < 4; ma++) {
            int row = arow0 + ma * 16;
            abase[ma] = (uint32_t)(row * 128 + ((ahi ^ (row & 7)) << 4));
        }
        // B tiles (per na-pair): {na0 k0, na0 k8, na1 k0, na1 k8}
        const int brow0 = wn * 64 + (lane & 7) + (lane >> 4) * 8;
        const int bhi   = (lane >> 3) & 1;
        #pragma unroll
        for (int np = 0; np < 4; np++) {
            int row = brow0 + np * 16;
            bbase[np] = (uint32_t)(TSZA + row * 128 + ((bhi ^ (row & 7)) << 4));
        }
    }

    float acc[4][8][4];
    #pragma unroll
    for (int i = 0; i < 4; i++)
        #pragma unroll
        for (int j = 0; j < 8; j++)
            #pragma unroll
            for (int q = 0; q < 4; q++) acc[i][j][q] = 0.0f;

    auto load_chunk = [&](int c, int s) {
        char* As = sm + s * STAGE;
        char* Bs = As + TSZA;
        #pragma unroll
        for (int i = 0; i < 4; i++) {            // A: 128 rows x 8 x 16B
            int id = tid + i * 256;
            int row = id >> 3, cj = id & 7;
            uint32_t swo = (uint32_t)(row * 128 + ((cj ^ (row & 7)) << 4));
            cpa16((uint32_t)__cvta_generic_to_shared(As + swo),
                  &g_A16[(((size_t)(bm + row) * NCHK + c) << 6) + (cj << 3)]);
        }
        #pragma unroll
        for (int i = 0; i < 8; i++) {            // B: 256 rows x 8 x 16B
            int id = tid + i * 256;
            int row = id >> 3, cj = id & 7;
            uint32_t swo = (uint32_t)(row * 128 + ((cj ^ (row & 7)) << 4));
            cpa16((uint32_t)__cvta_generic_to_shared(Bs + swo),
                  &g_B16[(((size_t)(bn + row) * NCHK + c) << 6) + (cj << 3)]);
        }
    };

    auto compute = [&](int s) {
        const uint32_t stg = sbase + (uint32_t)(s * STAGE);
        #pragma unroll
        for (int ka = 0; ka < 4; ka++) {
            const uint32_t kx = (uint32_t)(ka << 5);
            uint32_t a[4][4], bb[4][4];          // bb[np] = {b(2np)0,b(2np)1,b(2np+1)0,b(2np+1)1}
            #pragma unroll
            for (int ma = 0; ma < 4; ma++)
                ldm4(a[ma], stg + (abase[ma] ^ kx));
            #pragma unroll
            for (int np = 0; np < 4; np++)
                ldm4(bb[np], stg + (bbase[np] ^ kx));
            #pragma unroll
            for (int ma = 0; ma < 4; ma++)
                #pragma unroll
                for (int na = 0; na < 8; na++)
                    mma16f(acc[ma][na], a[ma], &bb[na >> 1][(na & 1) << 1]);
        }
    };

    // prologue: prefetch NS-1 chunks
    #pragma unroll
    for (int s = 0; s < NS - 1; s++) { load_chunk(s, s); CP_COMMIT(); }

    for (int c = 0; c < NCHK; c++) {
        CP_WAITN();
        __syncthreads();
        const int cn = c + NS - 1;
        if (cn < NCHK) { load_chunk(cn, cn & 3); CP_COMMIT(); }
        compute(c & 3);
    }

    // epilogue: C[r][co] -> out[b][co][l2], r = b*1024 + l2
    #pragma unroll
    for (int ma = 0; ma < 4; ma++) {
        #pragma unroll
        for (int half = 0; half < 2; half++) {
            const int r = bm + wm * 64 + ma * 16 + g + half * 8;
            const int b = r >> 10;
            const int l2 = r & (L2D - 1);
            float* op = out + (((size_t)b * NOUT) << 10) + l2;
            #pragma unroll
            for (int na = 0; na < 8; na++) {
                const int co = bn + wn * 64 + na * 8 + t * 2;
                op[(size_t)co << 10]       = acc[ma][na][half * 2 + 0];
                op[(size_t)(co + 1) << 10] = acc[ma][na][half * 2 + 1];
            }
        }
    }
}

// ---------------------------------------------------------------------------
extern "C" void kernel_launch(void* const* d_in, const int* in_sizes, int n_in,
                              void* d_out, int out_size) {
    const float* x = (const float*)d_in[0];
    const float* w = (const float*)d_in[1];
    if (n_in >= 2 && in_sizes[0] == 8 * 36 * 64) {   // defensive swap by size
        const float* tp = x; x = w; w = tp;
    }
    float* out = (float*)d_out;

    cudaFuncSetAttribute(gemm_kernel, cudaFuncAttributeMaxDynamicSharedMemorySize, SMEM_TOTAL);

    im2col_kernel<<<dim3(9, IN_CH, BATCH), 256>>>(x);
    beffT_kernel<<<dim3(KF / 256, NOUT), 256>>>(w);
    gemm_kernel<<<dim3(NOUT / 256, MROWS / 128), 256, SMEM_TOTAL>>>(out);
    (void)out_size;
}

// round 13
// speedup vs baseline: 1.4829x; 1.0568x over previous
#include <cuda_runtime.h>
#include <cuda_fp16.h>
#include <cstdint>

// ---------------- problem constants ----------------
#define IN_CH   256
#define BATCH   8
#define KF      2304            // 9*256
#define NOUT    512
#define L2D     1024
#define MROWS   (BATCH * L2D)   // 8192
#define NCHK    (KF / 64)       // 36 k-chunks of 64 (64 fp16 = 128B row)

// GEMM tiling: CTA 128(M) x 128(N), 8 warps (2m x 4n) of 64x32, 2 CTAs/SM
#define NS   3                  // cp.async pipeline stages
#define TSZA (128 * 128)        // 16KB
#define TSZB (128 * 128)        // 16KB
#define STAGE (TSZA + TSZB)     // 32KB
#define SMEM_TOTAL (NS * STAGE) // 96KB -> 2 CTAs per SM

// scratch (__device__ globals: allocation-free rule)
__device__ __align__(16) __half g_A16[(size_t)MROWS * KF];
__device__ __align__(16) __half g_B16[(size_t)NOUT * KF];

// ---------------- helpers ----------------
__device__ __forceinline__ uint32_t h2u(__half2 h) {
    uint32_t u;
    __builtin_memcpy(&u, &h, 4);
    return u;
}
__device__ __forceinline__ void cpa16(uint32_t dst, const void* src) {
    asm volatile("cp.async.cg.shared.global [%0], [%1], 16;" :: "r"(dst), "l"(src));
}
#define CP_COMMIT() asm volatile("cp.async.commit_group;" ::: "memory")
#define CP_WAITN()  asm volatile("cp.async.wait_group %0;" :: "n"(NS - 2) : "memory")

__device__ __forceinline__ void ldm4(uint32_t* r, uint32_t addr) {
    asm volatile("ldmatrix.sync.aligned.m8n8.x4.shared.b16 {%0,%1,%2,%3}, [%4];"
                 : "=r"(r[0]), "=r"(r[1]), "=r"(r[2]), "=r"(r[3]) : "r"(addr));
}
__device__ __forceinline__ void mma16f(float* c, const uint32_t* a, const uint32_t* b) {
    asm volatile(
        "mma.sync.aligned.m16n8k16.row.col.f32.f16.f16.f32 "
        "{%0,%1,%2,%3}, {%4,%5,%6,%7}, {%8,%9}, {%0,%1,%2,%3};"
        : "+f"(c[0]), "+f"(c[1]), "+f"(c[2]), "+f"(c[3])
        : "r"(a[0]), "r"(a[1]), "r"(a[2]), "r"(a[3]), "r"(b[0]), "r"(b[1]));
}

// ---------------------------------------------------------------------------
// Kernel 1: im2col -> chunked fp16, 4 elems/thread, one 8B store.
// ---------------------------------------------------------------------------
__global__ void im2col_kernel(const float* __restrict__ x) {
    const int dd = blockIdx.x, ci = blockIdx.y, b = blockIdx.z;
    const int oy = dd / 3 - 1, ox = dd % 3 - 1;          // uniform per block
    const float* xp = x + (((size_t)(b * IN_CH + ci)) << 10);
    const uint32_t ibase = ((uint32_t)(b * KF + ci * 9 + dd)) << 10;
    const uint32_t r0 = ibase / KF, k0 = ibase % KF;     // uniform per block

    const int l = threadIdx.x << 2;                      // 0,4,...,1020
    const int h = l >> 5, w = l & 31;                    // w multiple of 4
    const int y = h + oy;
    const bool yok = (unsigned)y < 32u;
    const float* rowp = xp + (y << 5) + (w + ox);
    float v[4];
    #pragma unroll
    for (int e = 0; e < 4; e++) {
        int xw = w + ox + e;
        v[e] = (yok && (unsigned)xw < 32u) ? rowp[e] : 0.0f;
    }
    uint32_t k = k0 + (uint32_t)l, r = r0;
    if (k >= KF) { k -= KF; r++; }
    uint2 pk;
    pk.x = h2u(__floats2half2_rn(v[0], v[1]));
    pk.y = h2u(__floats2half2_rn(v[2], v[3]));
    *(uint2*)&g_A16[(((size_t)r * NCHK + (k >> 6)) << 6) + (k & 63)] = pk;
}

// ---------------------------------------------------------------------------
// Kernel 2: B^T expansion -> chunked fp16. BT[co][k] = w[p][q][(j-m)&63]
// ---------------------------------------------------------------------------
__global__ void beffT_kernel(const float* __restrict__ wgt) {
    const int co = blockIdx.y;
    const int k = blockIdx.x * 256 + threadIdx.x;
    const int q = k >> 6, m = k & 63;
    const int p = co >> 6, j = co & 63;
    float v = wgt[((p * 36 + q) << 6) + ((j - m) & 63)];
    g_B16[(((size_t)co * NCHK + (k >> 6)) << 6) + (k & 63)] = __float2half(v);
}

// ---------------------------------------------------------------------------
// Kernel 3: fp16 mma.sync GEMM, ldmatrix frags, 2 CTAs/SM for bubble overlap.
// CTA 128x128, 8 warps (2m x 4n) of 64x32, 3-stage cp.async.
// ---------------------------------------------------------------------------
__global__ void __launch_bounds__(256, 2) gemm_kernel(float* __restrict__ out) {
    extern __shared__ char sm[];
    const uint32_t sbase = (uint32_t)__cvta_generic_to_shared(sm);
    const int tid = threadIdx.x;
    const int lane = tid & 31;
    const int wid = tid >> 5;
    const int g = lane >> 2, t = lane & 3;
    const int wm = wid >> 2, wn = wid & 3;       // 2m x 4n
    const int bm = blockIdx.y * 128;
    const int bn = blockIdx.x * 128;

    // ldmatrix per-lane base offsets (within a stage), ka=0
    uint32_t abase[4], bbase[2];
    {
        const int arow0 = wm * 64 + (lane & 7) + ((lane >> 3) & 1) * 8;
        const int ahi   = lane >> 4;
        #pragma unroll
        for (int ma = 0; ma < 4; ma++) {
            int row = arow0 + ma * 16;
            abase[ma] = (uint32_t)(row * 128 + ((ahi ^ (row & 7)) << 4));
        }
        const int brow0 = wn * 32 + (lane & 7) + (lane >> 4) * 8;
        const int bhi   = (lane >> 3) & 1;
        #pragma unroll
        for (int np = 0; np < 2; np++) {
            int row = brow0 + np * 16;
            bbase[np] = (uint32_t)(TSZA + row * 128 + ((bhi ^ (row & 7)) << 4));
        }
    }

    float acc[4][4][4];
    #pragma unroll
    for (int i = 0; i < 4; i++)
        #pragma unroll
        for (int j = 0; j < 4; j++)
            #pragma unroll
            for (int q = 0; q < 4; q++) acc[i][j][q] = 0.0f;

    auto load_chunk = [&](int c, int s) {
        char* As = sm + s * STAGE;
        char* Bs = As + TSZA;
        #pragma unroll
        for (int i = 0; i < 4; i++) {            // A & B: 128 rows x 8 x 16B each
            int id = tid + i * 256;
            int row = id >> 3, cj = id & 7;
            uint32_t swo = (uint32_t)(row * 128 + ((cj ^ (row & 7)) << 4));
            cpa16((uint32_t)__cvta_generic_to_shared(As + swo),
                  &g_A16[(((size_t)(bm + row) * NCHK + c) << 6) + (cj << 3)]);
            cpa16((uint32_t)__cvta_generic_to_shared(Bs + swo),
                  &g_B16[(((size_t)(bn + row) * NCHK + c) << 6) + (cj << 3)]);
        }
    };

    auto compute = [&](int s) {
        const uint32_t stg = sbase + (uint32_t)(s * STAGE);
        #pragma unroll
        for (int ka = 0; ka < 4; ka++) {
            const uint32_t kx = (uint32_t)(ka << 5);
            uint32_t a[4][4], bb[2][4];
            #pragma unroll
            for (int ma = 0; ma < 4; ma++)
                ldm4(a[ma], stg + (abase[ma] ^ kx));
            #pragma unroll
            for (int np = 0; np < 2; np++)
                ldm4(bb[np], stg + (bbase[np] ^ kx));
            #pragma unroll
            for (int ma = 0; ma < 4; ma++)
                #pragma unroll
                for (int na = 0; na < 4; na++)
                    mma16f(acc[ma][na], a[ma], &bb[na >> 1][(na & 1) << 1]);
        }
    };

    // prologue: prefetch NS-1 chunks
    #pragma unroll
    for (int s = 0; s < NS - 1; s++) { load_chunk(s, s); CP_COMMIT(); }

    int sc = 0, sn = NS - 1;                     // compute / next-load stage ids
    for (int c = 0; c < NCHK; c++) {
        CP_WAITN();
        __syncthreads();
        const int cn = c + NS - 1;
        if (cn < NCHK) { load_chunk(cn, sn); CP_COMMIT(); }
        compute(sc);
        sc = (sc + 1 == NS) ? 0 : sc + 1;
        sn = (sn + 1 == NS) ? 0 : sn + 1;
    }

    // epilogue: C[r][co] -> out[b][co][l2], r = b*1024 + l2
    #pragma unroll
    for (int ma = 0; ma < 4; ma++) {
        #pragma unroll
        for (int half = 0; half < 2; half++) {
            const int r = bm + wm * 64 + ma * 16 + g + half * 8;
            const int b = r >> 10;
            const int l2 = r & (L2D - 1);
            float* op = out + (((size_t)b * NOUT) << 10) + l2;
            #pragma unroll
            for (int na = 0; na < 4; na++) {
                const int co = bn + wn * 32 + na * 8 + t * 2;
                op[(size_t)co << 10]       = acc[ma][na][half * 2 + 0];
                op[(size_t)(co + 1) << 10] = acc[ma][na][half * 2 + 1];
            }
        }
    }
}

// ---------------------------------------------------------------------------
extern "C" void kernel_launch(void* const* d_in, const int* in_sizes, int n_in,
                              void* d_out, int out_size) {
    const float* x = (const float*)d_in[0];
    const float* w = (const float*)d_in[1];
    if (n_in >= 2 && in_sizes[0] == 8 * 36 * 64) {   // defensive swap by size
        const float* tp = x; x = w; w = tp;
    }
    float* out = (float*)d_out;

    cudaFuncSetAttribute(gemm_kernel, cudaFuncAttributeMaxDynamicSharedMemorySize, SMEM_TOTAL);

    im2col_kernel<<<dim3(9, IN_CH, BATCH), 256>>>(x);
    beffT_kernel<<<dim3(KF / 256, NOUT), 256>>>(w);
    gemm_kernel<<<dim3(NOUT / 128, MROWS / 128), 256, SMEM_TOTAL>>>(out);
    (void)out_size;
}